// round 2
// baseline (speedup 1.0000x reference)
#include <cuda_runtime.h>
#include <cuda_bf16.h>
#include <cstdint>

#define N_NODES 100000
#define F_HID 32

// ---------------- scratch (device globals; no allocation allowed) ----------
__device__ float g_P1[N_NODES * 32];   // x @ W1_l
__device__ float g_R1[N_NODES * 32];   // x @ W1_r
__device__ float g_S1[N_NODES * 32];   // segment-sum of P1 over edges
__device__ float g_H [N_NODES * 32];   // relu(S1/deg + b1 + R1)
__device__ float g_P2[N_NODES * 32];   // H @ W2_l
__device__ float g_R2[N_NODES * 32];   // H @ W2_r
__device__ float g_S2[N_NODES * 32];   // segment-sum of P2
__device__ float g_deg[N_NODES];
__device__ int   g_is64;               // edge_index dtype width flag

// ---------------- edge-index dtype detection --------------------------------
// int64 little-endian values < 2^31 have zero high words at odd int32 indices.
// Random int32 node ids make that pattern astronomically unlikely.
__global__ void detect_kernel(const int* __restrict__ ei) {
    if (threadIdx.x == 0 && blockIdx.x == 0) {
        int allzero = 1;
        #pragma unroll
        for (int i = 1; i < 64; i += 2)
            if (ei[i] != 0) { allzero = 0; break; }
        g_is64 = allzero;
    }
}

// ---------------- dual skinny GEMM: A[M,K] @ [Wl|Wr] (each K x 32) ----------
// BM=64, BN=64 tile, 256 threads, 4x4 micro-tile per thread, K chunked by 64.
template<int K>
__global__ void gemm_dual(const float* __restrict__ A,
                          const float* __restrict__ Wl,
                          const float* __restrict__ Wr,
                          float* __restrict__ P,
                          float* __restrict__ R,
                          int M)
{
    constexpr int KC  = (K < 64) ? K : 64;
    constexpr int LDA = KC + 4;
    __shared__ float As[64 * LDA];
    __shared__ float Bs[KC * 64];

    const int tid  = threadIdx.x;
    const int ty   = tid >> 4;
    const int tx   = tid & 15;
    const int row0 = blockIdx.x * 64;

    float acc[4][4] = {};

    for (int kc = 0; kc < K; kc += KC) {
        // load A chunk (coalesced float4, zero-pad OOB rows)
        #pragma unroll
        for (int idx = tid; idx < 64 * KC / 4; idx += 256) {
            int r  = idx / (KC / 4);
            int c4 = (idx % (KC / 4)) * 4;
            float4 v = make_float4(0.f, 0.f, 0.f, 0.f);
            int gr = row0 + r;
            if (gr < M) v = *(const float4*)(A + (size_t)gr * K + kc + c4);
            As[r * LDA + c4 + 0] = v.x;
            As[r * LDA + c4 + 1] = v.y;
            As[r * LDA + c4 + 2] = v.z;
            As[r * LDA + c4 + 3] = v.w;
        }
        // load B chunk: Bs[k][0..31]=Wl row, Bs[k][32..63]=Wr row
        #pragma unroll
        for (int idx = tid; idx < KC * 16; idx += 256) {
            int k  = idx >> 4;
            int j4 = (idx & 15) * 4;
            int gk = kc + k;
            float4 v = (j4 < 32) ? *(const float4*)(Wl + gk * 32 + j4)
                                 : *(const float4*)(Wr + gk * 32 + (j4 - 32));
            *(float4*)(Bs + k * 64 + j4) = v;
        }
        __syncthreads();

        #pragma unroll 8
        for (int k = 0; k < KC; k++) {
            float a0 = As[(ty * 4 + 0) * LDA + k];
            float a1 = As[(ty * 4 + 1) * LDA + k];
            float a2 = As[(ty * 4 + 2) * LDA + k];
            float a3 = As[(ty * 4 + 3) * LDA + k];
            float4 b = *(const float4*)(Bs + k * 64 + tx * 4);
            acc[0][0] += a0 * b.x; acc[0][1] += a0 * b.y; acc[0][2] += a0 * b.z; acc[0][3] += a0 * b.w;
            acc[1][0] += a1 * b.x; acc[1][1] += a1 * b.y; acc[1][2] += a1 * b.z; acc[1][3] += a1 * b.w;
            acc[2][0] += a2 * b.x; acc[2][1] += a2 * b.y; acc[2][2] += a2 * b.z; acc[2][3] += a2 * b.w;
            acc[3][0] += a3 * b.x; acc[3][1] += a3 * b.y; acc[3][2] += a3 * b.z; acc[3][3] += a3 * b.w;
        }
        __syncthreads();
    }

    #pragma unroll
    for (int i = 0; i < 4; i++) {
        int r = row0 + ty * 4 + i;
        if (r < M) {
            float4 v = make_float4(acc[i][0], acc[i][1], acc[i][2], acc[i][3]);
            int col = tx * 4;
            if (col < 32) *(float4*)(P + (size_t)r * 32 + col)        = v;
            else          *(float4*)(R + (size_t)r * 32 + col - 32)   = v;
        }
    }
}

// ---------------- edge aggregation: S[dst] += P[src] (vector f32 atomics) ---
template<bool ADD_DEG>
__global__ void edge_agg(const void* __restrict__ ei, int E,
                         const float* __restrict__ P,
                         float* __restrict__ S,
                         float* __restrict__ deg)
{
    int e = blockIdx.x * blockDim.x + threadIdx.x;
    if (e >= E) return;
    int s, d;
    if (g_is64) {
        const long long* p = (const long long*)ei;
        s = (int)p[e];
        d = (int)p[E + e];
    } else {
        const int* p = (const int*)ei;
        s = p[e];
        d = p[E + e];
    }
    const float4* pv = (const float4*)(P + (size_t)s * 32);
    float4*       qv = (float4*)(S + (size_t)d * 32);
    #pragma unroll
    for (int j = 0; j < 8; j++) {
        float4 v = __ldg(pv + j);
        asm volatile("red.global.add.v4.f32 [%0], {%1,%2,%3,%4};"
                     :: "l"(qv + j), "f"(v.x), "f"(v.y), "f"(v.z), "f"(v.w)
                     : "memory");
    }
    if (ADD_DEG) atomicAdd(deg + d, 1.0f);
}

// ---------------- elementwise: out = relu(S/max(deg,1) + b + R) ------------
__global__ void mean_bias_relu(const float* __restrict__ S,
                               const float* __restrict__ R,
                               const float* __restrict__ b,
                               const float* __restrict__ deg,
                               float* __restrict__ out, int n4)
{
    int i = blockIdx.x * blockDim.x + threadIdx.x;
    if (i >= n4) return;
    int node = i >> 3;
    int c    = (i & 7) * 4;
    float invd = 1.0f / fmaxf(deg[node], 1.0f);
    float4 s  = ((const float4*)S)[i];
    float4 r  = ((const float4*)R)[i];
    float4 bb = *(const float4*)(b + c);
    float4 o;
    o.x = fmaxf(fmaf(s.x, invd, bb.x) + r.x, 0.f);
    o.y = fmaxf(fmaf(s.y, invd, bb.y) + r.y, 0.f);
    o.z = fmaxf(fmaf(s.z, invd, bb.z) + r.z, 0.f);
    o.w = fmaxf(fmaf(s.w, invd, bb.w) + r.w, 0.f);
    ((float4*)out)[i] = o;
}

// ---------------- launcher --------------------------------------------------
extern "C" void kernel_launch(void* const* d_in, const int* in_sizes, int n_in,
                              void* d_out, int out_size)
{
    const float* x   = (const float*)d_in[0];
    const void*  ei  = d_in[1];
    const float* W1l = (const float*)d_in[2];
    const float* b1l = (const float*)d_in[3];
    const float* W1r = (const float*)d_in[4];
    const float* W2l = (const float*)d_in[5];
    const float* b2l = (const float*)d_in[6];
    const float* W2r = (const float*)d_in[7];
    float* out = (float*)d_out;

    const int E = in_sizes[1] / 2;
    const int M = N_NODES;

    float *P1, *R1, *S1, *H, *P2, *R2, *S2, *deg;
    cudaGetSymbolAddress((void**)&P1,  g_P1);
    cudaGetSymbolAddress((void**)&R1,  g_R1);
    cudaGetSymbolAddress((void**)&S1,  g_S1);
    cudaGetSymbolAddress((void**)&H,   g_H);
    cudaGetSymbolAddress((void**)&P2,  g_P2);
    cudaGetSymbolAddress((void**)&R2,  g_R2);
    cudaGetSymbolAddress((void**)&S2,  g_S2);
    cudaGetSymbolAddress((void**)&deg, g_deg);

    const size_t fbytes = (size_t)M * 32 * sizeof(float);
    cudaMemsetAsync(S1, 0, fbytes, 0);
    cudaMemsetAsync(S2, 0, fbytes, 0);
    cudaMemsetAsync(deg, 0, (size_t)M * sizeof(float), 0);

    detect_kernel<<<1, 32>>>((const int*)ei);

    const int gemm_blocks = (M + 63) / 64;
    const int edge_blocks = (E + 255) / 256;
    const int n4 = M * 8;
    const int ew_blocks = (n4 + 255) / 256;

    // Layer 1
    gemm_dual<128><<<gemm_blocks, 256>>>(x, W1l, W1r, P1, R1, M);
    edge_agg<true><<<edge_blocks, 256>>>(ei, E, P1, S1, deg);
    mean_bias_relu<<<ew_blocks, 256>>>(S1, R1, b1l, deg, H, n4);

    // Layer 2
    gemm_dual<32><<<gemm_blocks, 256>>>(H, W2l, W2r, P2, R2, M);
    edge_agg<false><<<edge_blocks, 256>>>(ei, E, P2, S2, deg);
    mean_bias_relu<<<ew_blocks, 256>>>(S2, R2, b2l, deg, out, n4);
}

// round 3
// speedup vs baseline: 1.5696x; 1.5696x over previous
#include <cuda_runtime.h>
#include <cuda_bf16.h>
#include <cstdint>

#define N_NODES 100000
#define E_MAX   1700000
#define SCAN_B  1024

// ---------------- scratch (device globals; no allocation allowed) ----------
__device__ float g_P1[N_NODES * 32];     // x @ W1_l
__device__ float g_R1[N_NODES * 32];     // x @ W1_r
__device__ float g_H [N_NODES * 32];     // layer-1 output
__device__ float g_P2[N_NODES * 32];     // H @ W2_l
__device__ float g_R2[N_NODES * 32];     // H @ W2_r
__device__ int   g_cnt[N_NODES];         // histogram / cursor
__device__ int   g_rowptr[N_NODES + 1];
__device__ int   g_col[E_MAX];
__device__ int   g_bsums[256];
__device__ int   g_is64;

// ---------------- edge-index dtype detection --------------------------------
__global__ void detect_kernel(const int* __restrict__ ei) {
    if (threadIdx.x == 0 && blockIdx.x == 0) {
        int allzero = 1;
        #pragma unroll
        for (int i = 1; i < 64; i += 2)
            if (ei[i] != 0) { allzero = 0; break; }
        g_is64 = allzero;
    }
}

__device__ __forceinline__ int load_idx(const void* ei, long long i) {
    return g_is64 ? (int)((const long long*)ei)[i] : ((const int*)ei)[i];
}

// ---------------- CSR build --------------------------------------------------
__global__ void count_edges(const void* __restrict__ ei, int E,
                            int* __restrict__ cnt) {
    int e = blockIdx.x * blockDim.x + threadIdx.x;
    if (e >= E) return;
    int d = load_idx(ei, (long long)E + e);
    atomicAdd(cnt + d, 1);
}

// per-block exclusive scan (Hillis-Steele inclusive, then shift)
__global__ void scan_blocks(const int* __restrict__ cnt,
                            int* __restrict__ rowptr,
                            int* __restrict__ bsums, int n) {
    __shared__ int sh[SCAN_B];
    int tid = threadIdx.x;
    int i = blockIdx.x * SCAN_B + tid;
    int v = (i < n) ? cnt[i] : 0;
    sh[tid] = v;
    __syncthreads();
    #pragma unroll
    for (int off = 1; off < SCAN_B; off <<= 1) {
        int t = (tid >= off) ? sh[tid - off] : 0;
        __syncthreads();
        sh[tid] += t;
        __syncthreads();
    }
    if (i < n) rowptr[i] = sh[tid] - v;          // exclusive
    if (tid == SCAN_B - 1) bsums[blockIdx.x] = sh[tid];
}

__global__ void scan_bsums(int* __restrict__ bsums, int nb) {
    if (threadIdx.x == 0) {
        int run = 0;
        for (int i = 0; i < nb; i++) { int v = bsums[i]; bsums[i] = run; run += v; }
    }
}

__global__ void add_offsets(int* __restrict__ rowptr,
                            const int* __restrict__ bsums, int n, int E) {
    int i = blockIdx.x * SCAN_B + threadIdx.x;
    if (i < n) rowptr[i] += bsums[blockIdx.x];
    if (i == 0) rowptr[n] = E;
}

__global__ void fill_csr(const void* __restrict__ ei, int E,
                         const int* __restrict__ rowptr,
                         int* __restrict__ cur, int* __restrict__ col) {
    int e = blockIdx.x * blockDim.x + threadIdx.x;
    if (e >= E) return;
    int s = load_idx(ei, e);
    int d = load_idx(ei, (long long)E + e);
    int pos = rowptr[d] + atomicAdd(cur + d, 1);
    col[pos] = s;
}

// ---------------- dual skinny GEMM: A[M,K] @ [Wl|Wr] (each K x 32) ----------
template<int K>
__global__ void gemm_dual(const float* __restrict__ A,
                          const float* __restrict__ Wl,
                          const float* __restrict__ Wr,
                          float* __restrict__ P,
                          float* __restrict__ R,
                          int M)
{
    constexpr int KC  = (K < 64) ? K : 64;
    constexpr int LDA = KC + 4;
    __shared__ float As[64 * LDA];
    __shared__ float Bs[KC * 64];

    const int tid  = threadIdx.x;
    const int ty   = tid >> 4;
    const int tx   = tid & 15;
    const int row0 = blockIdx.x * 64;

    float acc[4][4] = {};

    for (int kc = 0; kc < K; kc += KC) {
        #pragma unroll
        for (int idx = tid; idx < 64 * KC / 4; idx += 256) {
            int r  = idx / (KC / 4);
            int c4 = (idx % (KC / 4)) * 4;
            float4 v = make_float4(0.f, 0.f, 0.f, 0.f);
            int gr = row0 + r;
            if (gr < M) v = *(const float4*)(A + (size_t)gr * K + kc + c4);
            As[r * LDA + c4 + 0] = v.x;
            As[r * LDA + c4 + 1] = v.y;
            As[r * LDA + c4 + 2] = v.z;
            As[r * LDA + c4 + 3] = v.w;
        }
        #pragma unroll
        for (int idx = tid; idx < KC * 16; idx += 256) {
            int k  = idx >> 4;
            int j4 = (idx & 15) * 4;
            int gk = kc + k;
            float4 v = (j4 < 32) ? *(const float4*)(Wl + gk * 32 + j4)
                                 : *(const float4*)(Wr + gk * 32 + (j4 - 32));
            *(float4*)(Bs + k * 64 + j4) = v;
        }
        __syncthreads();

        #pragma unroll 8
        for (int k = 0; k < KC; k++) {
            float a0 = As[(ty * 4 + 0) * LDA + k];
            float a1 = As[(ty * 4 + 1) * LDA + k];
            float a2 = As[(ty * 4 + 2) * LDA + k];
            float a3 = As[(ty * 4 + 3) * LDA + k];
            float4 b = *(const float4*)(Bs + k * 64 + tx * 4);
            acc[0][0] += a0 * b.x; acc[0][1] += a0 * b.y; acc[0][2] += a0 * b.z; acc[0][3] += a0 * b.w;
            acc[1][0] += a1 * b.x; acc[1][1] += a1 * b.y; acc[1][2] += a1 * b.z; acc[1][3] += a1 * b.w;
            acc[2][0] += a2 * b.x; acc[2][1] += a2 * b.y; acc[2][2] += a2 * b.z; acc[2][3] += a2 * b.w;
            acc[3][0] += a3 * b.x; acc[3][1] += a3 * b.y; acc[3][2] += a3 * b.z; acc[3][3] += a3 * b.w;
        }
        __syncthreads();
    }

    #pragma unroll
    for (int i = 0; i < 4; i++) {
        int r = row0 + ty * 4 + i;
        if (r < M) {
            float4 v = make_float4(acc[i][0], acc[i][1], acc[i][2], acc[i][3]);
            int col = tx * 4;
            if (col < 32) *(float4*)(P + (size_t)r * 32 + col)      = v;
            else          *(float4*)(R + (size_t)r * 32 + col - 32) = v;
        }
    }
}

// ---------------- fused CSR aggregation + mean + bias + relu ----------------
// one warp per node: 32 lanes own the 32 feature columns
__global__ void agg_fused(const int* __restrict__ rowptr,
                          const int* __restrict__ col,
                          const float* __restrict__ P,
                          const float* __restrict__ R,
                          const float* __restrict__ b,
                          float* __restrict__ out)
{
    int warp = (blockIdx.x * blockDim.x + threadIdx.x) >> 5;
    int lane = threadIdx.x & 31;
    if (warp >= N_NODES) return;

    int beg = rowptr[warp];
    int end = rowptr[warp + 1];

    float acc = 0.f;
    int i = beg;
    for (; i + 4 <= end; i += 4) {
        int s0 = __ldg(col + i);
        int s1 = __ldg(col + i + 1);
        int s2 = __ldg(col + i + 2);
        int s3 = __ldg(col + i + 3);
        float v0 = __ldg(P + (size_t)s0 * 32 + lane);
        float v1 = __ldg(P + (size_t)s1 * 32 + lane);
        float v2 = __ldg(P + (size_t)s2 * 32 + lane);
        float v3 = __ldg(P + (size_t)s3 * 32 + lane);
        acc += (v0 + v1) + (v2 + v3);
    }
    for (; i < end; i++)
        acc += __ldg(P + (size_t)__ldg(col + i) * 32 + lane);

    float degf = (float)(end - beg);
    float mean = acc / fmaxf(degf, 1.0f);
    float r = R[(size_t)warp * 32 + lane];
    out[(size_t)warp * 32 + lane] = fmaxf(mean + b[lane] + r, 0.f);
}

// ---------------- launcher --------------------------------------------------
extern "C" void kernel_launch(void* const* d_in, const int* in_sizes, int n_in,
                              void* d_out, int out_size)
{
    const float* x   = (const float*)d_in[0];
    const void*  ei  = d_in[1];
    const float* W1l = (const float*)d_in[2];
    const float* b1l = (const float*)d_in[3];
    const float* W1r = (const float*)d_in[4];
    const float* W2l = (const float*)d_in[5];
    const float* b2l = (const float*)d_in[6];
    const float* W2r = (const float*)d_in[7];
    float* out = (float*)d_out;

    const int E = in_sizes[1] / 2;
    const int M = N_NODES;

    float *P1, *R1, *H, *P2, *R2;
    int *cnt, *rowptr, *colA, *bsums;
    cudaGetSymbolAddress((void**)&P1,     g_P1);
    cudaGetSymbolAddress((void**)&R1,     g_R1);
    cudaGetSymbolAddress((void**)&H,      g_H);
    cudaGetSymbolAddress((void**)&P2,     g_P2);
    cudaGetSymbolAddress((void**)&R2,     g_R2);
    cudaGetSymbolAddress((void**)&cnt,    g_cnt);
    cudaGetSymbolAddress((void**)&rowptr, g_rowptr);
    cudaGetSymbolAddress((void**)&colA,   g_col);
    cudaGetSymbolAddress((void**)&bsums,  g_bsums);

    detect_kernel<<<1, 32>>>((const int*)ei);

    // ---- CSR build (graph is identical for both layers) ----
    const int edge_blocks = (E + 255) / 256;
    const int scan_blocks_n = (M + SCAN_B - 1) / SCAN_B;

    cudaMemsetAsync(cnt, 0, M * sizeof(int), 0);
    count_edges<<<edge_blocks, 256>>>(ei, E, cnt);
    scan_blocks<<<scan_blocks_n, SCAN_B>>>(cnt, rowptr, bsums, M);
    scan_bsums<<<1, 32>>>(bsums, scan_blocks_n);
    add_offsets<<<scan_blocks_n, SCAN_B>>>(rowptr, bsums, M, E);
    cudaMemsetAsync(cnt, 0, M * sizeof(int), 0);
    fill_csr<<<edge_blocks, 256>>>(ei, E, rowptr, cnt, colA);

    const int gemm_blocks = (M + 63) / 64;
    const int agg_blocks  = (M * 32 + 255) / 256;

    // Layer 1
    gemm_dual<128><<<gemm_blocks, 256>>>(x, W1l, W1r, P1, R1, M);
    agg_fused<<<agg_blocks, 256>>>(rowptr, colA, P1, R1, b1l, H);

    // Layer 2
    gemm_dual<32><<<gemm_blocks, 256>>>(H, W2l, W2r, P2, R2, M);
    agg_fused<<<agg_blocks, 256>>>(rowptr, colA, P2, R2, b2l, out);
}

// round 4
// speedup vs baseline: 1.9544x; 1.2451x over previous
#include <cuda_runtime.h>
#include <cuda_bf16.h>
#include <cstdint>

#define N_NODES 100000
#define E_MAX   1700000
#define SCAN_B  1024

// ---------------- scratch (device globals; no allocation allowed) ----------
__device__ float g_P1[N_NODES * 32];
__device__ float g_R1[N_NODES * 32];
__device__ float g_H [N_NODES * 32];
__device__ float g_P2[N_NODES * 32];
__device__ float g_R2[N_NODES * 32];
__device__ int   g_cnt[N_NODES];
__device__ int   g_rowptr[N_NODES + 1];
__device__ int   g_col[E_MAX];
__device__ int   g_bsums[256];
__device__ int   g_is64;

// ---------------- edge-index dtype detection --------------------------------
__global__ void detect_kernel(const int* __restrict__ ei) {
    if (threadIdx.x == 0 && blockIdx.x == 0) {
        int allzero = 1;
        #pragma unroll
        for (int i = 1; i < 64; i += 2)
            if (ei[i] != 0) { allzero = 0; break; }
        g_is64 = allzero;
    }
}

__device__ __forceinline__ int load_idx(const void* ei, long long i) {
    return g_is64 ? (int)((const long long*)ei)[i] : ((const int*)ei)[i];
}

// ---------------- CSR build --------------------------------------------------
__global__ void count_edges(const void* __restrict__ ei, int E,
                            int* __restrict__ cnt) {
    int e = blockIdx.x * blockDim.x + threadIdx.x;
    if (e >= E) return;
    atomicAdd(cnt + load_idx(ei, (long long)E + e), 1);
}

__global__ void scan_blocks(const int* __restrict__ cnt,
                            int* __restrict__ rowptr,
                            int* __restrict__ bsums, int n) {
    __shared__ int sh[SCAN_B];
    int tid = threadIdx.x;
    int i = blockIdx.x * SCAN_B + tid;
    int v = (i < n) ? cnt[i] : 0;
    sh[tid] = v;
    __syncthreads();
    #pragma unroll
    for (int off = 1; off < SCAN_B; off <<= 1) {
        int t = (tid >= off) ? sh[tid - off] : 0;
        __syncthreads();
        sh[tid] += t;
        __syncthreads();
    }
    if (i < n) rowptr[i] = sh[tid] - v;
    if (tid == SCAN_B - 1) bsums[blockIdx.x] = sh[tid];
}

// parallel exclusive scan of block sums (nb <= 128)
__global__ void scan_bsums(int* __restrict__ bsums, int nb) {
    __shared__ int sh[128];
    int t = threadIdx.x;
    int v = (t < nb) ? bsums[t] : 0;
    sh[t] = v;
    __syncthreads();
    #pragma unroll
    for (int off = 1; off < 128; off <<= 1) {
        int u = (t >= off) ? sh[t - off] : 0;
        __syncthreads();
        sh[t] += u;
        __syncthreads();
    }
    if (t < nb) bsums[t] = sh[t] - v;
}

__global__ void add_offsets(int* __restrict__ rowptr,
                            const int* __restrict__ bsums, int n, int E) {
    int i = blockIdx.x * SCAN_B + threadIdx.x;
    if (i < n) rowptr[i] += bsums[blockIdx.x];
    if (i == 0) rowptr[n] = E;
}

__global__ void fill_csr(const void* __restrict__ ei, int E,
                         const int* __restrict__ rowptr,
                         int* __restrict__ cur, int* __restrict__ col) {
    int e = blockIdx.x * blockDim.x + threadIdx.x;
    if (e >= E) return;
    int s = load_idx(ei, e);
    int d = load_idx(ei, (long long)E + e);
    col[rowptr[d] + atomicAdd(cur + d, 1)] = s;
}

// ---------------- tf32 tensor-core dual GEMM: A[M,128] @ [Wl|Wr] ------------
// block = 256 thr (8 warps), M-tile 128 (warp w owns rows w*16..w*16+15),
// N = 64 full width per warp (8 n-tiles), K chunked by 16 through SMEM.
__device__ __forceinline__ uint32_t f2tf32(float f) {
    uint32_t u;
    asm("cvt.rna.tf32.f32 %0, %1;" : "=r"(u) : "f"(f));
    return u;
}

#define LDA_T 20   // 16 + 4 pad: conflict-free fragment loads
#define LDW_T 68   // 64 + 4 pad

__global__ __launch_bounds__(256, 2)
void gemm_tf32(const float* __restrict__ A,
               const float* __restrict__ Wl,
               const float* __restrict__ Wr,
               float* __restrict__ P,
               float* __restrict__ R, int M)
{
    __shared__ float As[128 * LDA_T];      // 10.0 KB
    __shared__ float Ws[128 * LDW_T];      // 34.0 KB

    const int tid  = threadIdx.x;
    const int wid  = tid >> 5;
    const int lane = tid & 31;
    const int row0 = blockIdx.x * 128;

    // stage all of W (=[Wl|Wr], 128x64) as tf32, once
    #pragma unroll
    for (int idx = tid; idx < 128 * 16; idx += 256) {
        int k  = idx >> 4;
        int j4 = (idx & 15) * 4;
        float4 v = (j4 < 32) ? *(const float4*)(Wl + k * 32 + j4)
                             : *(const float4*)(Wr + k * 32 + (j4 - 32));
        float4 o;
        o.x = __uint_as_float(f2tf32(v.x));
        o.y = __uint_as_float(f2tf32(v.y));
        o.z = __uint_as_float(f2tf32(v.z));
        o.w = __uint_as_float(f2tf32(v.w));
        *(float4*)(Ws + k * LDW_T + j4) = o;
    }

    float acc[8][4] = {};

    const int gr  = lane >> 2;   // group id 0..7
    const int gt  = lane & 3;    // thread in group 0..3

    for (int kc = 0; kc < 128; kc += 16) {
        // stage A chunk [128 rows x 16 k] as tf32
        #pragma unroll
        for (int idx = tid; idx < 128 * 4; idx += 256) {
            int r  = idx >> 2;
            int c4 = (idx & 3) * 4;
            float4 v = make_float4(0.f, 0.f, 0.f, 0.f);
            if (row0 + r < M) v = *(const float4*)(A + (size_t)(row0 + r) * 128 + kc + c4);
            float4 o;
            o.x = __uint_as_float(f2tf32(v.x));
            o.y = __uint_as_float(f2tf32(v.y));
            o.z = __uint_as_float(f2tf32(v.z));
            o.w = __uint_as_float(f2tf32(v.w));
            *(float4*)(As + r * LDA_T + c4) = o;
        }
        __syncthreads();

        #pragma unroll
        for (int kk = 0; kk < 2; kk++) {
            const uint32_t* asb = (const uint32_t*)As;
            const uint32_t* wsb = (const uint32_t*)Ws;
            int ra = wid * 16 + gr;
            int ca = kk * 8 + gt;
            uint32_t a0 = asb[ra * LDA_T + ca];
            uint32_t a1 = asb[(ra + 8) * LDA_T + ca];
            uint32_t a2 = asb[ra * LDA_T + ca + 4];
            uint32_t a3 = asb[(ra + 8) * LDA_T + ca + 4];
            int kb = kc + kk * 8;
            #pragma unroll
            for (int nt = 0; nt < 8; nt++) {
                uint32_t b0 = wsb[(kb + gt) * LDW_T + nt * 8 + gr];
                uint32_t b1 = wsb[(kb + gt + 4) * LDW_T + nt * 8 + gr];
                asm volatile(
                    "mma.sync.aligned.m16n8k8.row.col.f32.tf32.tf32.f32 "
                    "{%0,%1,%2,%3}, {%4,%5,%6,%7}, {%8,%9}, {%0,%1,%2,%3};"
                    : "+f"(acc[nt][0]), "+f"(acc[nt][1]),
                      "+f"(acc[nt][2]), "+f"(acc[nt][3])
                    : "r"(a0), "r"(a1), "r"(a2), "r"(a3), "r"(b0), "r"(b1));
            }
        }
        __syncthreads();
    }

    // epilogue: c0/c1 -> (r, col..col+1); c2/c3 -> (r+8, ...)
    int r = row0 + wid * 16 + gr;
    #pragma unroll
    for (int nt = 0; nt < 8; nt++) {
        int colg = nt * 8 + gt * 2;
        float* base = (nt < 4) ? P : R;
        int    c    = (nt < 4) ? colg : colg - 32;
        if (r < M)
            *(float2*)(base + (size_t)r * 32 + c) = make_float2(acc[nt][0], acc[nt][1]);
        if (r + 8 < M)
            *(float2*)(base + (size_t)(r + 8) * 32 + c) = make_float2(acc[nt][2], acc[nt][3]);
    }
}

// ---------------- fp32 dual GEMM (layer 2, K=32) ----------------------------
template<int K>
__global__ void gemm_dual(const float* __restrict__ A,
                          const float* __restrict__ Wl,
                          const float* __restrict__ Wr,
                          float* __restrict__ P,
                          float* __restrict__ R,
                          int M)
{
    constexpr int KC  = (K < 64) ? K : 64;
    constexpr int LDA = KC + 4;
    __shared__ float As[64 * LDA];
    __shared__ float Bs[KC * 64];

    const int tid  = threadIdx.x;
    const int ty   = tid >> 4;
    const int tx   = tid & 15;
    const int row0 = blockIdx.x * 64;

    float acc[4][4] = {};

    for (int kc = 0; kc < K; kc += KC) {
        #pragma unroll
        for (int idx = tid; idx < 64 * KC / 4; idx += 256) {
            int r  = idx / (KC / 4);
            int c4 = (idx % (KC / 4)) * 4;
            float4 v = make_float4(0.f, 0.f, 0.f, 0.f);
            int grr = row0 + r;
            if (grr < M) v = *(const float4*)(A + (size_t)grr * K + kc + c4);
            As[r * LDA + c4 + 0] = v.x;
            As[r * LDA + c4 + 1] = v.y;
            As[r * LDA + c4 + 2] = v.z;
            As[r * LDA + c4 + 3] = v.w;
        }
        #pragma unroll
        for (int idx = tid; idx < KC * 16; idx += 256) {
            int k  = idx >> 4;
            int j4 = (idx & 15) * 4;
            int gk = kc + k;
            float4 v = (j4 < 32) ? *(const float4*)(Wl + gk * 32 + j4)
                                 : *(const float4*)(Wr + gk * 32 + (j4 - 32));
            *(float4*)(Bs + k * 64 + j4) = v;
        }
        __syncthreads();

        #pragma unroll 8
        for (int k = 0; k < KC; k++) {
            float a0 = As[(ty * 4 + 0) * LDA + k];
            float a1 = As[(ty * 4 + 1) * LDA + k];
            float a2 = As[(ty * 4 + 2) * LDA + k];
            float a3 = As[(ty * 4 + 3) * LDA + k];
            float4 b = *(const float4*)(Bs + k * 64 + tx * 4);
            acc[0][0] += a0 * b.x; acc[0][1] += a0 * b.y; acc[0][2] += a0 * b.z; acc[0][3] += a0 * b.w;
            acc[1][0] += a1 * b.x; acc[1][1] += a1 * b.y; acc[1][2] += a1 * b.z; acc[1][3] += a1 * b.w;
            acc[2][0] += a2 * b.x; acc[2][1] += a2 * b.y; acc[2][2] += a2 * b.z; acc[2][3] += a2 * b.w;
            acc[3][0] += a3 * b.x; acc[3][1] += a3 * b.y; acc[3][2] += a3 * b.z; acc[3][3] += a3 * b.w;
        }
        __syncthreads();
    }

    #pragma unroll
    for (int i = 0; i < 4; i++) {
        int r = row0 + ty * 4 + i;
        if (r < M) {
            float4 v = make_float4(acc[i][0], acc[i][1], acc[i][2], acc[i][3]);
            int col = tx * 4;
            if (col < 32) *(float4*)(P + (size_t)r * 32 + col)      = v;
            else          *(float4*)(R + (size_t)r * 32 + col - 32) = v;
        }
    }
}

// ---------------- fused CSR aggregation + mean + bias + relu ----------------
__global__ __launch_bounds__(256)
void agg_fused(const int* __restrict__ rowptr,
               const int* __restrict__ col,
               const float* __restrict__ P,
               const float* __restrict__ R,
               const float* __restrict__ b,
               float* __restrict__ out)
{
    int warp = (blockIdx.x * blockDim.x + threadIdx.x) >> 5;
    int lane = threadIdx.x & 31;
    if (warp >= N_NODES) return;

    int beg = rowptr[warp];
    int end = rowptr[warp + 1];

    float acc = 0.f, acc2 = 0.f;
    int i = beg;
    for (; i + 8 <= end; i += 8) {
        int s0 = __ldg(col + i);
        int s1 = __ldg(col + i + 1);
        int s2 = __ldg(col + i + 2);
        int s3 = __ldg(col + i + 3);
        int s4 = __ldg(col + i + 4);
        int s5 = __ldg(col + i + 5);
        int s6 = __ldg(col + i + 6);
        int s7 = __ldg(col + i + 7);
        float v0 = __ldg(P + (size_t)s0 * 32 + lane);
        float v1 = __ldg(P + (size_t)s1 * 32 + lane);
        float v2 = __ldg(P + (size_t)s2 * 32 + lane);
        float v3 = __ldg(P + (size_t)s3 * 32 + lane);
        float v4 = __ldg(P + (size_t)s4 * 32 + lane);
        float v5 = __ldg(P + (size_t)s5 * 32 + lane);
        float v6 = __ldg(P + (size_t)s6 * 32 + lane);
        float v7 = __ldg(P + (size_t)s7 * 32 + lane);
        acc  += (v0 + v1) + (v2 + v3);
        acc2 += (v4 + v5) + (v6 + v7);
    }
    for (; i < end; i++)
        acc += __ldg(P + (size_t)__ldg(col + i) * 32 + lane);
    acc += acc2;

    float degf = (float)(end - beg);
    float mean = acc / fmaxf(degf, 1.0f);
    float r = R[(size_t)warp * 32 + lane];
    out[(size_t)warp * 32 + lane] = fmaxf(mean + b[lane] + r, 0.f);
}

// ---------------- launcher --------------------------------------------------
extern "C" void kernel_launch(void* const* d_in, const int* in_sizes, int n_in,
                              void* d_out, int out_size)
{
    const float* x   = (const float*)d_in[0];
    const void*  ei  = d_in[1];
    const float* W1l = (const float*)d_in[2];
    const float* b1l = (const float*)d_in[3];
    const float* W1r = (const float*)d_in[4];
    const float* W2l = (const float*)d_in[5];
    const float* b2l = (const float*)d_in[6];
    const float* W2r = (const float*)d_in[7];
    float* out = (float*)d_out;

    const int E = in_sizes[1] / 2;
    const int M = N_NODES;

    float *P1, *R1, *H, *P2, *R2;
    int *cnt, *rowptr, *colA, *bsums;
    cudaGetSymbolAddress((void**)&P1,     g_P1);
    cudaGetSymbolAddress((void**)&R1,     g_R1);
    cudaGetSymbolAddress((void**)&H,      g_H);
    cudaGetSymbolAddress((void**)&P2,     g_P2);
    cudaGetSymbolAddress((void**)&R2,     g_R2);
    cudaGetSymbolAddress((void**)&cnt,    g_cnt);
    cudaGetSymbolAddress((void**)&rowptr, g_rowptr);
    cudaGetSymbolAddress((void**)&colA,   g_col);
    cudaGetSymbolAddress((void**)&bsums,  g_bsums);

    const int edge_blocks   = (E + 255) / 256;
    const int scan_blocks_n = (M + SCAN_B - 1) / SCAN_B;

    detect_kernel<<<1, 32>>>((const int*)ei);
    cudaMemsetAsync(cnt, 0, M * sizeof(int), 0);
    count_edges<<<edge_blocks, 256>>>(ei, E, cnt);
    scan_blocks<<<scan_blocks_n, SCAN_B>>>(cnt, rowptr, bsums, M);
    scan_bsums<<<1, 128>>>(bsums, scan_blocks_n);

    // layer-1 projections (independent of CSR) — placed here so ncu -s 5 can land on it
    gemm_tf32<<<(M + 127) / 128, 256>>>(x, W1l, W1r, P1, R1, M);

    add_offsets<<<scan_blocks_n, SCAN_B>>>(rowptr, bsums, M, E);
    cudaMemsetAsync(cnt, 0, M * sizeof(int), 0);
    fill_csr<<<edge_blocks, 256>>>(ei, E, rowptr, cnt, colA);

    const int agg_blocks = (M * 32 + 255) / 256;

    agg_fused<<<agg_blocks, 256>>>(rowptr, colA, P1, R1, b1l, H);
    gemm_dual<32><<<(M + 63) / 64, 256>>>(H, W2l, W2r, P2, R2, M);
    agg_fused<<<agg_blocks, 256>>>(rowptr, colA, P2, R2, b2l, out);
}

// round 5
// speedup vs baseline: 2.1010x; 1.0750x over previous
#include <cuda_runtime.h>
#include <cuda_bf16.h>
#include <cstdint>

#define N_NODES 100000
#define E_MAX   1700000
#define SCAN_B  1024

// ---------------- scratch (device globals; no allocation allowed) ----------
__device__ float g_P1[N_NODES * 32];
__device__ float g_R1[N_NODES * 32];
__device__ float g_H [N_NODES * 32];
__device__ float g_P2[N_NODES * 32];
__device__ float g_R2[N_NODES * 32];
__device__ int   g_cnt[N_NODES];
__device__ int   g_rowptr[N_NODES + 1];
__device__ int   g_col[E_MAX];
__device__ int   g_bsums[128];
__device__ int   g_is64;

// ---------------- zero cnt + edge-index dtype detection ---------------------
__global__ void zero_and_detect(int* __restrict__ cnt, const int* __restrict__ ei) {
    int i = blockIdx.x * blockDim.x + threadIdx.x;
    if (i < N_NODES) cnt[i] = 0;
    if (i == 0) {
        int allzero = 1;
        #pragma unroll
        for (int j = 1; j < 64; j += 2)
            if (ei[j] != 0) { allzero = 0; break; }
        g_is64 = allzero;
    }
}

__device__ __forceinline__ int load_idx(const void* ei, long long i) {
    return g_is64 ? (int)((const long long*)ei)[i] : ((const int*)ei)[i];
}

// ---------------- CSR build --------------------------------------------------
__global__ void count_edges(const void* __restrict__ ei, int E,
                            int* __restrict__ cnt) {
    int e = blockIdx.x * blockDim.x + threadIdx.x;
    if (e >= E) return;
    atomicAdd(cnt + load_idx(ei, (long long)E + e), 1);
}

__global__ void scan_blocks(const int* __restrict__ cnt,
                            int* __restrict__ rowptr,
                            int* __restrict__ bsums, int n) {
    __shared__ int sh[SCAN_B];
    int tid = threadIdx.x;
    int i = blockIdx.x * SCAN_B + tid;
    int v = (i < n) ? cnt[i] : 0;
    sh[tid] = v;
    __syncthreads();
    #pragma unroll
    for (int off = 1; off < SCAN_B; off <<= 1) {
        int t = (tid >= off) ? sh[tid - off] : 0;
        __syncthreads();
        sh[tid] += t;
        __syncthreads();
    }
    if (i < n) rowptr[i] = sh[tid] - v;
    if (tid == SCAN_B - 1) bsums[blockIdx.x] = sh[tid];
}

// each block computes its own bsums prefix with one warp, then offsets rows
__global__ void add_offsets(int* __restrict__ rowptr,
                            const int* __restrict__ bsums, int n, int E) {
    __shared__ int carry;
    int b = blockIdx.x;
    if (threadIdx.x < 32) {
        int sum = 0;
        for (int j = (int)threadIdx.x; j < b; j += 32) sum += bsums[j];
        #pragma unroll
        for (int o = 16; o; o >>= 1) sum += __shfl_xor_sync(0xffffffffu, sum, o);
        if (threadIdx.x == 0) carry = sum;
    }
    __syncthreads();
    int i = b * SCAN_B + threadIdx.x;
    if (i < n) rowptr[i] += carry;
    if (i == 0) rowptr[n] = E;
}

// cnt[d] holds degree; atomicSub hands out slots [0, deg) and leaves cnt at 0
__global__ void fill_csr(const void* __restrict__ ei, int E,
                         const int* __restrict__ rowptr,
                         int* __restrict__ cur, int* __restrict__ col) {
    int e = blockIdx.x * blockDim.x + threadIdx.x;
    if (e >= E) return;
    int s = load_idx(ei, e);
    int d = load_idx(ei, (long long)E + e);
    col[rowptr[d] + atomicSub(cur + d, 1) - 1] = s;
}

// ---------------- tf32 tensor-core dual GEMM: A[M,K] @ [Wl|Wr] --------------
__device__ __forceinline__ uint32_t f2tf32(float f) {
    uint32_t u;
    asm("cvt.rna.tf32.f32 %0, %1;" : "=r"(u) : "f"(f));
    return u;
}

#define LDA_T 20
#define LDW_T 68

template<int K>
__global__ __launch_bounds__(256, 2)
void gemm_tf32(const float* __restrict__ A,
               const float* __restrict__ Wl,
               const float* __restrict__ Wr,
               float* __restrict__ P,
               float* __restrict__ R, int M)
{
    __shared__ float As[128 * LDA_T];
    __shared__ float Ws[K * LDW_T];

    const int tid  = threadIdx.x;
    const int wid  = tid >> 5;
    const int lane = tid & 31;
    const int row0 = blockIdx.x * 128;

    // stage W (=[Wl|Wr], Kx64) as tf32, once
    #pragma unroll
    for (int idx = tid; idx < K * 16; idx += 256) {
        int k  = idx >> 4;
        int j4 = (idx & 15) * 4;
        float4 v = (j4 < 32) ? *(const float4*)(Wl + k * 32 + j4)
                             : *(const float4*)(Wr + k * 32 + (j4 - 32));
        float4 o;
        o.x = __uint_as_float(f2tf32(v.x));
        o.y = __uint_as_float(f2tf32(v.y));
        o.z = __uint_as_float(f2tf32(v.z));
        o.w = __uint_as_float(f2tf32(v.w));
        *(float4*)(Ws + k * LDW_T + j4) = o;
    }

    float acc[8][4] = {};
    const int gr = lane >> 2;
    const int gt = lane & 3;

    for (int kc = 0; kc < K; kc += 16) {
        #pragma unroll
        for (int idx = tid; idx < 128 * 4; idx += 256) {
            int r  = idx >> 2;
            int c4 = (idx & 3) * 4;
            float4 v = make_float4(0.f, 0.f, 0.f, 0.f);
            if (row0 + r < M) v = *(const float4*)(A + (size_t)(row0 + r) * K + kc + c4);
            float4 o;
            o.x = __uint_as_float(f2tf32(v.x));
            o.y = __uint_as_float(f2tf32(v.y));
            o.z = __uint_as_float(f2tf32(v.z));
            o.w = __uint_as_float(f2tf32(v.w));
            *(float4*)(As + r * LDA_T + c4) = o;
        }
        __syncthreads();

        #pragma unroll
        for (int kk = 0; kk < 2; kk++) {
            const uint32_t* asb = (const uint32_t*)As;
            const uint32_t* wsb = (const uint32_t*)Ws;
            int ra = wid * 16 + gr;
            int ca = kk * 8 + gt;
            uint32_t a0 = asb[ra * LDA_T + ca];
            uint32_t a1 = asb[(ra + 8) * LDA_T + ca];
            uint32_t a2 = asb[ra * LDA_T + ca + 4];
            uint32_t a3 = asb[(ra + 8) * LDA_T + ca + 4];
            int kb = kc + kk * 8;
            #pragma unroll
            for (int nt = 0; nt < 8; nt++) {
                uint32_t b0 = wsb[(kb + gt) * LDW_T + nt * 8 + gr];
                uint32_t b1 = wsb[(kb + gt + 4) * LDW_T + nt * 8 + gr];
                asm volatile(
                    "mma.sync.aligned.m16n8k8.row.col.f32.tf32.tf32.f32 "
                    "{%0,%1,%2,%3}, {%4,%5,%6,%7}, {%8,%9}, {%0,%1,%2,%3};"
                    : "+f"(acc[nt][0]), "+f"(acc[nt][1]),
                      "+f"(acc[nt][2]), "+f"(acc[nt][3])
                    : "r"(a0), "r"(a1), "r"(a2), "r"(a3), "r"(b0), "r"(b1));
            }
        }
        __syncthreads();
    }

    int r = row0 + wid * 16 + gr;
    #pragma unroll
    for (int nt = 0; nt < 8; nt++) {
        int colg = nt * 8 + gt * 2;
        float* base = (nt < 4) ? P : R;
        int    c    = (nt < 4) ? colg : colg - 32;
        if (r < M)
            *(float2*)(base + (size_t)r * 32 + c) = make_float2(acc[nt][0], acc[nt][1]);
        if (r + 8 < M)
            *(float2*)(base + (size_t)(r + 8) * 32 + c) = make_float2(acc[nt][2], acc[nt][3]);
    }
}

// ---------------- fused CSR aggregation + mean + bias + relu (float4) -------
// one warp per node; lane = (q, c): q = edge slot 0..3, c = float4 col 0..7
__device__ __forceinline__ void f4add(float4& a, const float4& v) {
    a.x += v.x; a.y += v.y; a.z += v.z; a.w += v.w;
}

__global__ __launch_bounds__(256)
void agg_fused(const int* __restrict__ rowptr,
               const int* __restrict__ col,
               const float* __restrict__ P,
               const float* __restrict__ R,
               const float* __restrict__ b,
               float* __restrict__ out)
{
    int warp = (blockIdx.x * blockDim.x + threadIdx.x) >> 5;
    int lane = threadIdx.x & 31;
    if (warp >= N_NODES) return;

    const int q = lane >> 3;
    const int c = lane & 7;

    int beg = rowptr[warp];
    int end = rowptr[warp + 1];

    float4 a0 = make_float4(0.f, 0.f, 0.f, 0.f);
    float4 a1 = make_float4(0.f, 0.f, 0.f, 0.f);

    int i = beg;
    for (; i + 8 <= end; i += 8) {
        int s0 = __ldg(col + i + q);
        int s1 = __ldg(col + i + 4 + q);
        float4 v0 = __ldg((const float4*)(P + (size_t)s0 * 32) + c);
        float4 v1 = __ldg((const float4*)(P + (size_t)s1 * 32) + c);
        f4add(a0, v0);
        f4add(a1, v1);
    }
    for (; i < end; i += 4) {
        int e = i + q;
        if (e < end) {
            int s = __ldg(col + e);
            float4 v = __ldg((const float4*)(P + (size_t)s * 32) + c);
            f4add(a0, v);
        }
    }
    f4add(a0, a1);

    // reduce over the 4 edge-slot groups (xor 8, 16)
    #pragma unroll
    for (int o = 8; o <= 16; o <<= 1) {
        a0.x += __shfl_xor_sync(0xffffffffu, a0.x, o);
        a0.y += __shfl_xor_sync(0xffffffffu, a0.y, o);
        a0.z += __shfl_xor_sync(0xffffffffu, a0.z, o);
        a0.w += __shfl_xor_sync(0xffffffffu, a0.w, o);
    }

    if (q == 0) {
        float invd = 1.0f / fmaxf((float)(end - beg), 1.0f);
        float4 r  = __ldg((const float4*)(R + (size_t)warp * 32) + c);
        float4 bb = __ldg((const float4*)b + c);
        float4 o;
        o.x = fmaxf(fmaf(a0.x, invd, bb.x) + r.x, 0.f);
        o.y = fmaxf(fmaf(a0.y, invd, bb.y) + r.y, 0.f);
        o.z = fmaxf(fmaf(a0.z, invd, bb.z) + r.z, 0.f);
        o.w = fmaxf(fmaf(a0.w, invd, bb.w) + r.w, 0.f);
        *((float4*)(out + (size_t)warp * 32) + c) = o;
    }
}

// ---------------- launcher --------------------------------------------------
extern "C" void kernel_launch(void* const* d_in, const int* in_sizes, int n_in,
                              void* d_out, int out_size)
{
    const float* x   = (const float*)d_in[0];
    const void*  ei  = d_in[1];
    const float* W1l = (const float*)d_in[2];
    const float* b1l = (const float*)d_in[3];
    const float* W1r = (const float*)d_in[4];
    const float* W2l = (const float*)d_in[5];
    const float* b2l = (const float*)d_in[6];
    const float* W2r = (const float*)d_in[7];
    float* out = (float*)d_out;

    const int E = in_sizes[1] / 2;
    const int M = N_NODES;

    float *P1, *R1, *H, *P2, *R2;
    int *cnt, *rowptr, *colA, *bsums;
    cudaGetSymbolAddress((void**)&P1,     g_P1);
    cudaGetSymbolAddress((void**)&R1,     g_R1);
    cudaGetSymbolAddress((void**)&H,      g_H);
    cudaGetSymbolAddress((void**)&P2,     g_P2);
    cudaGetSymbolAddress((void**)&R2,     g_R2);
    cudaGetSymbolAddress((void**)&cnt,    g_cnt);
    cudaGetSymbolAddress((void**)&rowptr, g_rowptr);
    cudaGetSymbolAddress((void**)&colA,   g_col);
    cudaGetSymbolAddress((void**)&bsums,  g_bsums);

    const int edge_blocks   = (E + 255) / 256;
    const int scan_blocks_n = (M + SCAN_B - 1) / SCAN_B;

    zero_and_detect<<<(M + 1023) / 1024, 1024>>>(cnt, (const int*)ei);
    count_edges<<<edge_blocks, 256>>>(ei, E, cnt);

    // layer-1 projections (independent of CSR build)
    gemm_tf32<128><<<(M + 127) / 128, 256>>>(x, W1l, W1r, P1, R1, M);

    scan_blocks<<<scan_blocks_n, SCAN_B>>>(cnt, rowptr, bsums, M);
    add_offsets<<<scan_blocks_n, SCAN_B>>>(rowptr, bsums, M, E);
    fill_csr<<<edge_blocks, 256>>>(ei, E, rowptr, cnt, colA);

    const int agg_blocks = (M * 32 + 255) / 256;

    agg_fused<<<agg_blocks, 256>>>(rowptr, colA, P1, R1, b1l, H);
    gemm_tf32<32><<<(M + 127) / 128, 256>>>(H, W2l, W2r, P2, R2, M);
    agg_fused<<<agg_blocks, 256>>>(rowptr, colA, P2, R2, b2l, out);
}

// round 6
// speedup vs baseline: 2.1248x; 1.0113x over previous
#include <cuda_runtime.h>
#include <cuda_bf16.h>
#include <cstdint>

#define N_NODES 100000
#define E_MAX   1700000
#define SCAN_B  1024

// ---------------- scratch (device globals; no allocation allowed) ----------
__device__ float g_P1[N_NODES * 32];
__device__ float g_R1[N_NODES * 32];
__device__ float g_H [N_NODES * 32];
__device__ float g_P2[N_NODES * 32];
__device__ float g_R2[N_NODES * 32];
__device__ int   g_cnt[N_NODES];
__device__ int   g_rowptr[N_NODES + 1];
__device__ int   g_col[E_MAX];
__device__ int   g_bsums[128];
__device__ int   g_is64;

// ---------------- zero cnt + edge-index dtype detection ---------------------
__global__ void zero_and_detect(int* __restrict__ cnt, const int* __restrict__ ei) {
    int i = blockIdx.x * blockDim.x + threadIdx.x;
    if (i < N_NODES) cnt[i] = 0;
    if (i == 0) {
        int allzero = 1;
        #pragma unroll
        for (int j = 1; j < 64; j += 2)
            if (ei[j] != 0) { allzero = 0; break; }
        g_is64 = allzero;
    }
}

__device__ __forceinline__ int load_idx(const void* ei, long long i) {
    return g_is64 ? (int)((const long long*)ei)[i] : ((const int*)ei)[i];
}

// ---------------- CSR build --------------------------------------------------
__global__ void count_edges(const void* __restrict__ ei, int E,
                            int* __restrict__ cnt) {
    int e = blockIdx.x * blockDim.x + threadIdx.x;
    if (e >= E) return;
    atomicAdd(cnt + load_idx(ei, (long long)E + e), 1);
}

// warp-shuffle block scan (exclusive out), 1024 threads
__global__ void scan_blocks(const int* __restrict__ cnt,
                            int* __restrict__ rowptr,
                            int* __restrict__ bsums, int n) {
    __shared__ int wsum[32];
    int tid  = threadIdx.x;
    int wid  = tid >> 5;
    int lane = tid & 31;
    int i = blockIdx.x * SCAN_B + tid;
    int v = (i < n) ? cnt[i] : 0;

    int incl = v;
    #pragma unroll
    for (int o = 1; o < 32; o <<= 1) {
        int t = __shfl_up_sync(0xffffffffu, incl, o);
        if (lane >= o) incl += t;
    }
    if (lane == 31) wsum[wid] = incl;
    __syncthreads();
    if (wid == 0) {
        int s = wsum[lane];
        int si = s;
        #pragma unroll
        for (int o = 1; o < 32; o <<= 1) {
            int t = __shfl_up_sync(0xffffffffu, si, o);
            if (lane >= o) si += t;
        }
        wsum[lane] = si - s;   // exclusive warp offsets
    }
    __syncthreads();
    incl += wsum[wid];
    if (i < n) rowptr[i] = incl - v;
    if (tid == SCAN_B - 1) bsums[blockIdx.x] = incl;
}

// each block computes its own bsums prefix with one warp, then offsets rows
__global__ void add_offsets(int* __restrict__ rowptr,
                            const int* __restrict__ bsums, int n, int E) {
    __shared__ int carry;
    int b = blockIdx.x;
    if (threadIdx.x < 32) {
        int sum = 0;
        for (int j = (int)threadIdx.x; j < b; j += 32) sum += bsums[j];
        #pragma unroll
        for (int o = 16; o; o >>= 1) sum += __shfl_xor_sync(0xffffffffu, sum, o);
        if (threadIdx.x == 0) carry = sum;
    }
    __syncthreads();
    int i = b * SCAN_B + threadIdx.x;
    if (i < n) rowptr[i] += carry;
    if (i == 0) rowptr[n] = E;
}

// cnt[d] holds degree; atomicSub hands out slots and leaves cnt back at 0
__global__ void fill_csr(const void* __restrict__ ei, int E,
                         const int* __restrict__ rowptr,
                         int* __restrict__ cur, int* __restrict__ col) {
    int e = blockIdx.x * blockDim.x + threadIdx.x;
    if (e >= E) return;
    int s = load_idx(ei, e);
    int d = load_idx(ei, (long long)E + e);
    col[rowptr[d] + atomicSub(cur + d, 1) - 1] = s;
}

// ---------------- tf32 tensor-core dual GEMM: A[M,K] @ [Wl|Wr] --------------
__device__ __forceinline__ uint32_t f2tf32(float f) {
    uint32_t u;
    asm("cvt.rna.tf32.f32 %0, %1;" : "=r"(u) : "f"(f));
    return u;
}

#define LDA_T 20
#define LDW_T 68

template<int K>
__global__ __launch_bounds__(256, 2)
void gemm_tf32(const float* __restrict__ A,
               const float* __restrict__ Wl,
               const float* __restrict__ Wr,
               float* __restrict__ P,
               float* __restrict__ R, int M)
{
    __shared__ float As[128 * LDA_T];
    __shared__ float Ws[K * LDW_T];

    const int tid  = threadIdx.x;
    const int wid  = tid >> 5;
    const int lane = tid & 31;
    const int row0 = blockIdx.x * 128;

    #pragma unroll
    for (int idx = tid; idx < K * 16; idx += 256) {
        int k  = idx >> 4;
        int j4 = (idx & 15) * 4;
        float4 v = (j4 < 32) ? *(const float4*)(Wl + k * 32 + j4)
                             : *(const float4*)(Wr + k * 32 + (j4 - 32));
        float4 o;
        o.x = __uint_as_float(f2tf32(v.x));
        o.y = __uint_as_float(f2tf32(v.y));
        o.z = __uint_as_float(f2tf32(v.z));
        o.w = __uint_as_float(f2tf32(v.w));
        *(float4*)(Ws + k * LDW_T + j4) = o;
    }

    float acc[8][4] = {};
    const int gr = lane >> 2;
    const int gt = lane & 3;

    for (int kc = 0; kc < K; kc += 16) {
        #pragma unroll
        for (int idx = tid; idx < 128 * 4; idx += 256) {
            int r  = idx >> 2;
            int c4 = (idx & 3) * 4;
            float4 v = make_float4(0.f, 0.f, 0.f, 0.f);
            if (row0 + r < M) v = *(const float4*)(A + (size_t)(row0 + r) * K + kc + c4);
            float4 o;
            o.x = __uint_as_float(f2tf32(v.x));
            o.y = __uint_as_float(f2tf32(v.y));
            o.z = __uint_as_float(f2tf32(v.z));
            o.w = __uint_as_float(f2tf32(v.w));
            *(float4*)(As + r * LDA_T + c4) = o;
        }
        __syncthreads();

        #pragma unroll
        for (int kk = 0; kk < 2; kk++) {
            const uint32_t* asb = (const uint32_t*)As;
            const uint32_t* wsb = (const uint32_t*)Ws;
            int ra = wid * 16 + gr;
            int ca = kk * 8 + gt;
            uint32_t a0 = asb[ra * LDA_T + ca];
            uint32_t a1 = asb[(ra + 8) * LDA_T + ca];
            uint32_t a2 = asb[ra * LDA_T + ca + 4];
            uint32_t a3 = asb[(ra + 8) * LDA_T + ca + 4];
            int kb = kc + kk * 8;
            #pragma unroll
            for (int nt = 0; nt < 8; nt++) {
                uint32_t b0 = wsb[(kb + gt) * LDW_T + nt * 8 + gr];
                uint32_t b1 = wsb[(kb + gt + 4) * LDW_T + nt * 8 + gr];
                asm volatile(
                    "mma.sync.aligned.m16n8k8.row.col.f32.tf32.tf32.f32 "
                    "{%0,%1,%2,%3}, {%4,%5,%6,%7}, {%8,%9}, {%0,%1,%2,%3};"
                    : "+f"(acc[nt][0]), "+f"(acc[nt][1]),
                      "+f"(acc[nt][2]), "+f"(acc[nt][3])
                    : "r"(a0), "r"(a1), "r"(a2), "r"(a3), "r"(b0), "r"(b1));
            }
        }
        __syncthreads();
    }

    int r = row0 + wid * 16 + gr;
    #pragma unroll
    for (int nt = 0; nt < 8; nt++) {
        int colg = nt * 8 + gt * 2;
        float* base = (nt < 4) ? P : R;
        int    c    = (nt < 4) ? colg : colg - 32;
        if (r < M)
            *(float2*)(base + (size_t)r * 32 + c) = make_float2(acc[nt][0], acc[nt][1]);
        if (r + 8 < M)
            *(float2*)(base + (size_t)(r + 8) * 32 + c) = make_float2(acc[nt][2], acc[nt][3]);
    }
}

// ---------------- fused CSR aggregation + mean + bias + relu (float4) -------
// one warp per node; lane = (q, c): q = edge slot 0..3, c = float4 col 0..7
// 16-edge unrolled body: 4 independent col LDGs + 4 independent LDG.128s.
__device__ __forceinline__ void f4add(float4& a, const float4& v) {
    a.x += v.x; a.y += v.y; a.z += v.z; a.w += v.w;
}

__global__ __launch_bounds__(256)
void agg_fused(const int* __restrict__ rowptr,
               const int* __restrict__ col,
               const float* __restrict__ P,
               const float* __restrict__ R,
               const float* __restrict__ b,
               float* __restrict__ out)
{
    int warp = (blockIdx.x * blockDim.x + threadIdx.x) >> 5;
    int lane = threadIdx.x & 31;
    if (warp >= N_NODES) return;

    const int q = lane >> 3;
    const int c = lane & 7;

    int beg = rowptr[warp];
    int end = rowptr[warp + 1];

    float4 a0 = make_float4(0.f, 0.f, 0.f, 0.f);
    float4 a1 = make_float4(0.f, 0.f, 0.f, 0.f);

    int i = beg;
    for (; i + 16 <= end; i += 16) {
        int s0 = __ldg(col + i +      q);
        int s1 = __ldg(col + i +  4 + q);
        int s2 = __ldg(col + i +  8 + q);
        int s3 = __ldg(col + i + 12 + q);
        float4 v0 = __ldg((const float4*)(P + (size_t)s0 * 32) + c);
        float4 v1 = __ldg((const float4*)(P + (size_t)s1 * 32) + c);
        float4 v2 = __ldg((const float4*)(P + (size_t)s2 * 32) + c);
        float4 v3 = __ldg((const float4*)(P + (size_t)s3 * 32) + c);
        f4add(a0, v0);
        f4add(a1, v1);
        f4add(a0, v2);
        f4add(a1, v3);
    }
    if (i + 8 <= end) {
        int s0 = __ldg(col + i +     q);
        int s1 = __ldg(col + i + 4 + q);
        float4 v0 = __ldg((const float4*)(P + (size_t)s0 * 32) + c);
        float4 v1 = __ldg((const float4*)(P + (size_t)s1 * 32) + c);
        f4add(a0, v0);
        f4add(a1, v1);
        i += 8;
    }
    for (; i < end; i += 4) {
        int e = i + q;
        if (e < end) {
            int s = __ldg(col + e);
            float4 v = __ldg((const float4*)(P + (size_t)s * 32) + c);
            f4add(a0, v);
        }
    }
    f4add(a0, a1);

    #pragma unroll
    for (int o = 8; o <= 16; o <<= 1) {
        a0.x += __shfl_xor_sync(0xffffffffu, a0.x, o);
        a0.y += __shfl_xor_sync(0xffffffffu, a0.y, o);
        a0.z += __shfl_xor_sync(0xffffffffu, a0.z, o);
        a0.w += __shfl_xor_sync(0xffffffffu, a0.w, o);
    }

    if (q == 0) {
        float invd = 1.0f / fmaxf((float)(end - beg), 1.0f);
        float4 r  = __ldg((const float4*)(R + (size_t)warp * 32) + c);
        float4 bb = __ldg((const float4*)b + c);
        float4 o;
        o.x = fmaxf(fmaf(a0.x, invd, bb.x) + r.x, 0.f);
        o.y = fmaxf(fmaf(a0.y, invd, bb.y) + r.y, 0.f);
        o.z = fmaxf(fmaf(a0.z, invd, bb.z) + r.z, 0.f);
        o.w = fmaxf(fmaf(a0.w, invd, bb.w) + r.w, 0.f);
        *((float4*)(out + (size_t)warp * 32) + c) = o;
    }
}

// ---------------- launcher --------------------------------------------------
extern "C" void kernel_launch(void* const* d_in, const int* in_sizes, int n_in,
                              void* d_out, int out_size)
{
    const float* x   = (const float*)d_in[0];
    const void*  ei  = d_in[1];
    const float* W1l = (const float*)d_in[2];
    const float* b1l = (const float*)d_in[3];
    const float* W1r = (const float*)d_in[4];
    const float* W2l = (const float*)d_in[5];
    const float* b2l = (const float*)d_in[6];
    const float* W2r = (const float*)d_in[7];
    float* out = (float*)d_out;

    const int E = in_sizes[1] / 2;
    const int M = N_NODES;

    float *P1, *R1, *H, *P2, *R2;
    int *cnt, *rowptr, *colA, *bsums;
    cudaGetSymbolAddress((void**)&P1,     g_P1);
    cudaGetSymbolAddress((void**)&R1,     g_R1);
    cudaGetSymbolAddress((void**)&H,      g_H);
    cudaGetSymbolAddress((void**)&P2,     g_P2);
    cudaGetSymbolAddress((void**)&R2,     g_R2);
    cudaGetSymbolAddress((void**)&cnt,    g_cnt);
    cudaGetSymbolAddress((void**)&rowptr, g_rowptr);
    cudaGetSymbolAddress((void**)&colA,   g_col);
    cudaGetSymbolAddress((void**)&bsums,  g_bsums);

    const int edge_blocks   = (E + 255) / 256;
    const int scan_blocks_n = (M + SCAN_B - 1) / SCAN_B;

    zero_and_detect<<<(M + 1023) / 1024, 1024>>>(cnt, (const int*)ei);
    count_edges<<<edge_blocks, 256>>>(ei, E, cnt);

    // layer-1 projections (independent of CSR build)
    gemm_tf32<128><<<(M + 127) / 128, 256>>>(x, W1l, W1r, P1, R1, M);

    scan_blocks<<<scan_blocks_n, SCAN_B>>>(cnt, rowptr, bsums, M);
    add_offsets<<<scan_blocks_n, SCAN_B>>>(rowptr, bsums, M, E);
    fill_csr<<<edge_blocks, 256>>>(ei, E, rowptr, cnt, colA);

    const int agg_blocks = (M * 32 + 255) / 256;

    agg_fused<<<agg_blocks, 256>>>(rowptr, colA, P1, R1, b1l, H);
    gemm_tf32<32><<<(M + 127) / 128, 256>>>(H, W2l, W2r, P2, R2, M);
    agg_fused<<<agg_blocks, 256>>>(rowptr, colA, P2, R2, b2l, out);
}

// round 8
// speedup vs baseline: 2.3143x; 1.0892x over previous
#include <cuda_runtime.h>
#include <cuda_bf16.h>
#include <cstdint>

#define N_NODES 100000
#define E_MAX   1700000
#define SCAN_B  256

// ---------------- scratch (device globals; no allocation allowed) ----------
__device__ float g_P1[N_NODES * 32];
__device__ float g_R1[N_NODES * 32];
__device__ float g_H [N_NODES * 32];
__device__ float g_P2[N_NODES * 32];
__device__ float g_R2[N_NODES * 32];
__device__ int   g_cnt[N_NODES];
__device__ int   g_rowptr[N_NODES + 1];
__device__ int   g_col[E_MAX];
__device__ int   g_bsums[512];
__device__ int   g_is64;

// ---------------- zero cnt + edge-index dtype detection ---------------------
__global__ void zero_and_detect(int* __restrict__ cnt, const int* __restrict__ ei) {
    cudaGridDependencySynchronize();
    int i = blockIdx.x * blockDim.x + threadIdx.x;
    if (i < N_NODES) cnt[i] = 0;
    if (i == 0) {
        int allzero = 1;
        #pragma unroll
        for (int j = 1; j < 64; j += 2)
            if (ei[j] != 0) { allzero = 0; break; }
        g_is64 = allzero;
    }
}

__device__ __forceinline__ int load_idx(const void* ei, long long i) {
    return g_is64 ? (int)((const long long*)ei)[i] : ((const int*)ei)[i];
}

// ---------------- CSR build --------------------------------------------------
__global__ void count_edges(const void* __restrict__ ei, int E,
                            int* __restrict__ cnt) {
    cudaGridDependencySynchronize();
    int e = blockIdx.x * blockDim.x + threadIdx.x;
    if (e >= E) return;
    atomicAdd(cnt + load_idx(ei, (long long)E + e), 1);
}

// warp-shuffle block scan (exclusive out), SCAN_B = 256 threads
__global__ void scan_blocks(const int* __restrict__ cnt,
                            int* __restrict__ rowptr,
                            int* __restrict__ bsums, int n) {
    cudaGridDependencySynchronize();
    __shared__ int wsum[8];
    int tid  = threadIdx.x;
    int wid  = tid >> 5;
    int lane = tid & 31;
    int i = blockIdx.x * SCAN_B + tid;
    int v = (i < n) ? cnt[i] : 0;

    int incl = v;
    #pragma unroll
    for (int o = 1; o < 32; o <<= 1) {
        int t = __shfl_up_sync(0xffffffffu, incl, o);
        if (lane >= o) incl += t;
    }
    if (lane == 31) wsum[wid] = incl;
    __syncthreads();
    if (wid == 0 && lane < 8) {
        int s = wsum[lane];
        int si = s;
        #pragma unroll
        for (int o = 1; o < 8; o <<= 1) {
            int t = __shfl_up_sync(0xffu, si, o);
            if (lane >= o) si += t;
        }
        wsum[lane] = si - s;
    }
    __syncthreads();
    incl += wsum[wid];
    if (i < n) rowptr[i] = incl - v;
    if (tid == SCAN_B - 1) bsums[blockIdx.x] = incl;
}

// each block computes its own bsums prefix with one warp, then offsets rows
__global__ void add_offsets(int* __restrict__ rowptr,
                            const int* __restrict__ bsums, int n, int E) {
    cudaGridDependencySynchronize();
    __shared__ int carry;
    int b = blockIdx.x;
    if (threadIdx.x < 32) {
        int sum = 0;
        for (int j = (int)threadIdx.x; j < b; j += 32) sum += bsums[j];
        #pragma unroll
        for (int o = 16; o; o >>= 1) sum += __shfl_xor_sync(0xffffffffu, sum, o);
        if (threadIdx.x == 0) carry = sum;
    }
    __syncthreads();
    int i = b * SCAN_B + threadIdx.x;
    if (i < n) rowptr[i] += carry;
    if (i == 0) rowptr[n] = E;
}

// cnt[d] holds degree; atomicSub hands out slots and leaves cnt back at 0
__global__ void fill_csr(const void* __restrict__ ei, int E,
                         const int* __restrict__ rowptr,
                         int* __restrict__ cur, int* __restrict__ col) {
    cudaGridDependencySynchronize();
    int e = blockIdx.x * blockDim.x + threadIdx.x;
    if (e >= E) return;
    int s = load_idx(ei, e);
    int d = load_idx(ei, (long long)E + e);
    col[rowptr[d] + atomicSub(cur + d, 1) - 1] = s;
}

// ---------------- tf32 tensor-core dual GEMM: A[M,K] @ [Wl|Wr] --------------
__device__ __forceinline__ uint32_t f2tf32(float f) {
    uint32_t u;
    asm("cvt.rna.tf32.f32 %0, %1;" : "=r"(u) : "f"(f));
    return u;
}

#define LDA_T 20
#define LDW_T 68

template<int K>
__global__ __launch_bounds__(256, 2)
void gemm_tf32(const float* __restrict__ A,
               const float* __restrict__ Wl,
               const float* __restrict__ Wr,
               float* __restrict__ P,
               float* __restrict__ R, int M)
{
    cudaGridDependencySynchronize();
    __shared__ float As[128 * LDA_T];
    __shared__ float Ws[K * LDW_T];

    const int tid  = threadIdx.x;
    const int wid  = tid >> 5;
    const int lane = tid & 31;
    const int row0 = blockIdx.x * 128;

    #pragma unroll
    for (int idx = tid; idx < K * 16; idx += 256) {
        int k  = idx >> 4;
        int j4 = (idx & 15) * 4;
        float4 v = (j4 < 32) ? *(const float4*)(Wl + k * 32 + j4)
                             : *(const float4*)(Wr + k * 32 + (j4 - 32));
        float4 o;
        o.x = __uint_as_float(f2tf32(v.x));
        o.y = __uint_as_float(f2tf32(v.y));
        o.z = __uint_as_float(f2tf32(v.z));
        o.w = __uint_as_float(f2tf32(v.w));
        *(float4*)(Ws + k * LDW_T + j4) = o;
    }

    float acc[8][4] = {};
    const int gr = lane >> 2;
    const int gt = lane & 3;

    for (int kc = 0; kc < K; kc += 16) {
        #pragma unroll
        for (int idx = tid; idx < 128 * 4; idx += 256) {
            int r  = idx >> 2;
            int c4 = (idx & 3) * 4;
            float4 v = make_float4(0.f, 0.f, 0.f, 0.f);
            if (row0 + r < M) v = *(const float4*)(A + (size_t)(row0 + r) * K + kc + c4);
            float4 o;
            o.x = __uint_as_float(f2tf32(v.x));
            o.y = __uint_as_float(f2tf32(v.y));
            o.z = __uint_as_float(f2tf32(v.z));
            o.w = __uint_as_float(f2tf32(v.w));
            *(float4*)(As + r * LDA_T + c4) = o;
        }
        __syncthreads();

        #pragma unroll
        for (int kk = 0; kk < 2; kk++) {
            const uint32_t* asb = (const uint32_t*)As;
            const uint32_t* wsb = (const uint32_t*)Ws;
            int ra = wid * 16 + gr;
            int ca = kk * 8 + gt;
            uint32_t a0 = asb[ra * LDA_T + ca];
            uint32_t a1 = asb[(ra + 8) * LDA_T + ca];
            uint32_t a2 = asb[ra * LDA_T + ca + 4];
            uint32_t a3 = asb[(ra + 8) * LDA_T + ca + 4];
            int kb = kc + kk * 8;
            #pragma unroll
            for (int nt = 0; nt < 8; nt++) {
                uint32_t b0 = wsb[(kb + gt) * LDW_T + nt * 8 + gr];
                uint32_t b1 = wsb[(kb + gt + 4) * LDW_T + nt * 8 + gr];
                asm volatile(
                    "mma.sync.aligned.m16n8k8.row.col.f32.tf32.tf32.f32 "
                    "{%0,%1,%2,%3}, {%4,%5,%6,%7}, {%8,%9}, {%0,%1,%2,%3};"
                    : "+f"(acc[nt][0]), "+f"(acc[nt][1]),
                      "+f"(acc[nt][2]), "+f"(acc[nt][3])
                    : "r"(a0), "r"(a1), "r"(a2), "r"(a3), "r"(b0), "r"(b1));
            }
        }
        __syncthreads();
    }

    int r = row0 + wid * 16 + gr;
    #pragma unroll
    for (int nt = 0; nt < 8; nt++) {
        int colg = nt * 8 + gt * 2;
        float* base = (nt < 4) ? P : R;
        int    c    = (nt < 4) ? colg : colg - 32;
        if (r < M)
            *(float2*)(base + (size_t)r * 32 + c) = make_float2(acc[nt][0], acc[nt][1]);
        if (r + 8 < M)
            *(float2*)(base + (size_t)(r + 8) * 32 + c) = make_float2(acc[nt][2], acc[nt][3]);
    }
}

// ---------------- fused CSR aggregation + mean + bias + relu (float4) -------
__device__ __forceinline__ void f4add(float4& a, const float4& v) {
    a.x += v.x; a.y += v.y; a.z += v.z; a.w += v.w;
}

__global__ __launch_bounds__(256)
void agg_fused(const int* __restrict__ rowptr,
               const int* __restrict__ col,
               const float* __restrict__ P,
               const float* __restrict__ R,
               const float* __restrict__ b,
               float* __restrict__ out)
{
    cudaGridDependencySynchronize();
    int warp = (blockIdx.x * blockDim.x + threadIdx.x) >> 5;
    int lane = threadIdx.x & 31;
    if (warp >= N_NODES) return;

    const int q = lane >> 3;
    const int c = lane & 7;

    int beg = rowptr[warp];
    int end = rowptr[warp + 1];

    float4 a0 = make_float4(0.f, 0.f, 0.f, 0.f);
    float4 a1 = make_float4(0.f, 0.f, 0.f, 0.f);

    int i = beg;
    for (; i + 16 <= end; i += 16) {
        int s0 = __ldg(col + i +      q);
        int s1 = __ldg(col + i +  4 + q);
        int s2 = __ldg(col + i +  8 + q);
        int s3 = __ldg(col + i + 12 + q);
        float4 v0 = __ldg((const float4*)(P + (size_t)s0 * 32) + c);
        float4 v1 = __ldg((const float4*)(P + (size_t)s1 * 32) + c);
        float4 v2 = __ldg((const float4*)(P + (size_t)s2 * 32) + c);
        float4 v3 = __ldg((const float4*)(P + (size_t)s3 * 32) + c);
        f4add(a0, v0);
        f4add(a1, v1);
        f4add(a0, v2);
        f4add(a1, v3);
    }
    if (i + 8 <= end) {
        int s0 = __ldg(col + i +     q);
        int s1 = __ldg(col + i + 4 + q);
        float4 v0 = __ldg((const float4*)(P + (size_t)s0 * 32) + c);
        float4 v1 = __ldg((const float4*)(P + (size_t)s1 * 32) + c);
        f4add(a0, v0);
        f4add(a1, v1);
        i += 8;
    }
    for (; i < end; i += 4) {
        int e = i + q;
        if (e < end) {
            int s = __ldg(col + e);
            float4 v = __ldg((const float4*)(P + (size_t)s * 32) + c);
            f4add(a0, v);
        }
    }
    f4add(a0, a1);

    #pragma unroll
    for (int o = 8; o <= 16; o <<= 1) {
        a0.x += __shfl_xor_sync(0xffffffffu, a0.x, o);
        a0.y += __shfl_xor_sync(0xffffffffu, a0.y, o);
        a0.z += __shfl_xor_sync(0xffffffffu, a0.z, o);
        a0.w += __shfl_xor_sync(0xffffffffu, a0.w, o);
    }

    if (q == 0) {
        float invd = 1.0f / fmaxf((float)(end - beg), 1.0f);
        float4 r  = __ldg((const float4*)(R + (size_t)warp * 32) + c);
        float4 bb = __ldg((const float4*)b + c);
        float4 o;
        o.x = fmaxf(fmaf(a0.x, invd, bb.x) + r.x, 0.f);
        o.y = fmaxf(fmaf(a0.y, invd, bb.y) + r.y, 0.f);
        o.z = fmaxf(fmaf(a0.z, invd, bb.z) + r.z, 0.f);
        o.w = fmaxf(fmaf(a0.w, invd, bb.w) + r.w, 0.f);
        *((float4*)(out + (size_t)warp * 32) + c) = o;
    }
}

// ---------------- PDL launch helper -----------------------------------------
template<typename F, typename... Args>
static inline void launch_pdl(F* k, dim3 grid, dim3 block, Args... args) {
    cudaLaunchConfig_t cfg = {};
    cfg.gridDim  = grid;
    cfg.blockDim = block;
    cfg.dynamicSmemBytes = 0;
    cfg.stream = 0;
    cudaLaunchAttribute at[1];
    at[0].id = cudaLaunchAttributeProgrammaticStreamSerialization;
    at[0].val.programmaticStreamSerializationAllowed = 1;
    cfg.attrs = at;
    cfg.numAttrs = 1;
    cudaLaunchKernelEx(&cfg, k, args...);
}

// ---------------- launcher --------------------------------------------------
extern "C" void kernel_launch(void* const* d_in, const int* in_sizes, int n_in,
                              void* d_out, int out_size)
{
    const float* x   = (const float*)d_in[0];
    const void*  ei  = d_in[1];
    const float* W1l = (const float*)d_in[2];
    const float* b1l = (const float*)d_in[3];
    const float* W1r = (const float*)d_in[4];
    const float* W2l = (const float*)d_in[5];
    const float* b2l = (const float*)d_in[6];
    const float* W2r = (const float*)d_in[7];
    float* out = (float*)d_out;

    const int E = in_sizes[1] / 2;
    const int M = N_NODES;

    float *P1, *R1, *H, *P2, *R2;
    int *cnt, *rowptr, *colA, *bsums;
    cudaGetSymbolAddress((void**)&P1,     g_P1);
    cudaGetSymbolAddress((void**)&R1,     g_R1);
    cudaGetSymbolAddress((void**)&H,      g_H);
    cudaGetSymbolAddress((void**)&P2,     g_P2);
    cudaGetSymbolAddress((void**)&R2,     g_R2);
    cudaGetSymbolAddress((void**)&cnt,    g_cnt);
    cudaGetSymbolAddress((void**)&rowptr, g_rowptr);
    cudaGetSymbolAddress((void**)&colA,   g_col);
    cudaGetSymbolAddress((void**)&bsums,  g_bsums);

    // one-time side stream + events (created on first, non-captured call)
    static cudaStream_t s_side = [](){
        cudaStream_t s; cudaStreamCreateWithFlags(&s, cudaStreamNonBlocking); return s;
    }();
    static cudaEvent_t s_evFork = [](){
        cudaEvent_t e; cudaEventCreateWithFlags(&e, cudaEventDisableTiming); return e;
    }();
    static cudaEvent_t s_evJoin = [](){
        cudaEvent_t e; cudaEventCreateWithFlags(&e, cudaEventDisableTiming); return e;
    }();

    const int edge_blocks   = (E + 255) / 256;
    const int scan_blocks_n = (M + SCAN_B - 1) / SCAN_B;
    const int agg_blocks    = (M * 32 + 255) / 256;

    // fork: gemm1 (depends only on x/W) runs on side stream concurrently
    // with the CSR build chain on stream 0
    cudaEventRecord(s_evFork, 0);
    cudaStreamWaitEvent(s_side, s_evFork, 0);
    gemm_tf32<128><<<(M + 127) / 128, 256, 0, s_side>>>(x, W1l, W1r, P1, R1, M);
    cudaEventRecord(s_evJoin, s_side);

    // CSR build chain on stream 0 (PDL-serialized)
    launch_pdl(zero_and_detect, dim3((M + 1023) / 1024), dim3(1024), cnt, (const int*)ei);
    launch_pdl(count_edges, dim3(edge_blocks), dim3(256), ei, E, cnt);
    launch_pdl(scan_blocks, dim3(scan_blocks_n), dim3(SCAN_B), (const int*)cnt, rowptr, bsums, M);
    launch_pdl(add_offsets, dim3(scan_blocks_n), dim3(SCAN_B), rowptr, (const int*)bsums, M, E);
    launch_pdl(fill_csr, dim3(edge_blocks), dim3(256), ei, E, (const int*)rowptr, cnt, colA);

    // join: agg1 needs both CSR (stream 0) and P1/R1 (side stream)
    cudaStreamWaitEvent(0, s_evJoin, 0);

    launch_pdl(agg_fused, dim3(agg_blocks), dim3(256),
               (const int*)rowptr, (const int*)colA,
               (const float*)P1, (const float*)R1, b1l, H);
    launch_pdl(gemm_tf32<32>, dim3((M + 127) / 128), dim3(256),
               (const float*)H, W2l, W2r, P2, R2, M);
    launch_pdl(agg_fused, dim3(agg_blocks), dim3(256),
               (const int*)rowptr, (const int*)colA,
               (const float*)P2, (const float*)R2, b2l, out);
}